// round 7
// baseline (speedup 1.0000x reference)
#include <cuda_runtime.h>
#include <cuda_bf16.h>
#include <stdint.h>

#define BB 4
#define NN 2048
#define MM 8192
#define DD 128
#define SS 1024    // NUM_SEGMENTS
#define HB 8       // sort blocks per batch (source)
#define HBT 2      // sort blocks per batch (target)
#define NSRC_BLKS (BB * HB)            // 32
#define NTGT_BLKS (BB * HBT)           // 8
#define NBLK (NSRC_BLKS + NTGT_BLKS)   // 40 (all co-resident on 148 SMs)

// ---------------- scratch (static __device__, no allocation) ----------------
__device__ int g_blkhist_s[BB * HB * SS];
__device__ int g_blkhist_t[BB * HBT * SS];
__device__ int g_cnt_s[BB * SS];
__device__ int g_off_s[BB * SS];
__device__ int g_cnt_t[BB * SS];
__device__ int g_off_t[BB * SS];
__device__ int g_rows_s[BB * MM];   // source rows grouped by segment
__device__ int g_rows_t[BB * NN];   // target rows grouped by segment

// barrier state (monotone generation -> safe across graph replays)
__device__ unsigned g_bar_count = 0;
__device__ unsigned g_bar_gen   = 0;

__device__ __forceinline__ void sort_barrier() {
    __syncthreads();
    if (threadIdx.x == 0) {
        unsigned gen = *((volatile unsigned*)&g_bar_gen);
        __threadfence();
        if (atomicAdd(&g_bar_count, 1u) == NBLK - 1u) {
            atomicExch(&g_bar_count, 0u);
            __threadfence();
            atomicAdd(&g_bar_gen, 1u);
        } else {
            while (*((volatile unsigned*)&g_bar_gen) == gen) { }
        }
        __threadfence();
    }
    __syncthreads();
}

// ---------------- 1) fused sort: hist -> barrier -> scan+scatter ----------------
// blocks 0..31: source indices (8 blocks/batch); blocks 32..39: target (2/batch)
__global__ __launch_bounds__(256) void k_sort(const int* __restrict__ idx_src,
                                              const int* __restrict__ idx_tgt) {
    __shared__ int sh[SS];      // hist, then cursors
    __shared__ int wsum[8];
    const int t = threadIdx.x;
    const int lane = t & 31;
    const int w = t >> 5;

    int b, i, nblk;
    const int* hist;
    const int* in;
    int *rows, *cnt_out, *off_out, *my_hist;
    if (blockIdx.x < NSRC_BLKS) {
        b = blockIdx.x >> 3; i = blockIdx.x & 7; nblk = HB;
        hist = g_blkhist_s + b * HB * SS;
        in   = idx_src + b * MM + i * 1024;
        rows = g_rows_s + b * MM;
        cnt_out = g_cnt_s + b * SS; off_out = g_off_s + b * SS;
        my_hist = g_blkhist_s + (b * HB + i) * SS;
    } else {
        int u = blockIdx.x - NSRC_BLKS;
        b = u >> 1; i = u & 1; nblk = HBT;
        hist = g_blkhist_t + b * HBT * SS;
        in   = idx_tgt + b * NN + i * 1024;
        rows = g_rows_t + b * NN;
        cnt_out = g_cnt_t + b * SS; off_out = g_off_t + b * SS;
        my_hist = g_blkhist_t + (b * HBT + i) * SS;
    }

    // ---- phase A: private histogram (indices stay in registers) ----
    ((int4*)sh)[t] = make_int4(0, 0, 0, 0);
    __syncthreads();
    const int4 a = ((const int4*)in)[t];
    atomicAdd(&sh[a.x], 1); atomicAdd(&sh[a.y], 1);
    atomicAdd(&sh[a.z], 1); atomicAdd(&sh[a.w], 1);
    __syncthreads();
    ((int4*)my_hist)[t] = ((int4*)sh)[t];

    // ---- all 40 blocks' histograms globally visible ----
    sort_barrier();

    // ---- phase B: scan + scatter ----
    int4 tot = make_int4(0, 0, 0, 0);
    int4 pre = make_int4(0, 0, 0, 0);
    for (int j = 0; j < nblk; j++) {
        int4 h4 = ((const int4*)(hist + j * SS))[t];
        tot.x += h4.x; tot.y += h4.y; tot.z += h4.z; tot.w += h4.w;
        if (j < i) { pre.x += h4.x; pre.y += h4.y; pre.z += h4.z; pre.w += h4.w; }
    }
    int l0 = tot.x, l1 = l0 + tot.y, l2 = l1 + tot.z, l3 = l2 + tot.w;

    int inc = l3;
    #pragma unroll
    for (int d = 1; d < 32; d <<= 1) {
        int up = __shfl_up_sync(0xffffffffu, inc, d);
        if (lane >= d) inc += up;
    }
    if (lane == 31) wsum[w] = inc;
    __syncthreads();
    if (w == 0) {
        int v = (lane < 8) ? wsum[lane] : 0;
        #pragma unroll
        for (int d = 1; d < 8; d <<= 1) {
            int up = __shfl_up_sync(0xffffffffu, v, d);
            if (lane >= d) v += up;
        }
        if (lane < 8) wsum[lane] = v;
    }
    __syncthreads();
    int excl = inc - l3 + (w > 0 ? wsum[w - 1] : 0);

    int o0 = excl, o1 = excl + l0, o2 = excl + l1, o3 = excl + l2;

    if (i == 0) {
        int s = 4 * t;
        cnt_out[s + 0] = tot.x;  off_out[s + 0] = o0;
        cnt_out[s + 1] = tot.y;  off_out[s + 1] = o1;
        cnt_out[s + 2] = tot.z;  off_out[s + 2] = o2;
        cnt_out[s + 3] = tot.w;  off_out[s + 3] = o3;
    }

    sh[4 * t + 0] = o0 + pre.x;
    sh[4 * t + 1] = o1 + pre.y;
    sh[4 * t + 2] = o2 + pre.z;
    sh[4 * t + 3] = o3 + pre.w;
    __syncthreads();

    int m = i * 1024 + 4 * t;
    int q;
    q = atomicAdd(&sh[a.x], 1); rows[q] = m + 0;
    q = atomicAdd(&sh[a.y], 1); rows[q] = m + 1;
    q = atomicAdd(&sh[a.z], 1); rows[q] = m + 2;
    q = atomicAdd(&sh[a.w], 1); rows[q] = m + 3;
}

// ---------------- 2) segsum + direct write to target rows ----------------
__global__ __launch_bounds__(128) void k_segsum_write(const float* __restrict__ src,
                                                      float* __restrict__ out) {
    int seg  = (blockIdx.x * blockDim.x + threadIdx.x) >> 5;  // 0..BB*SS-1
    int lane = threadIdx.x & 31;
    if (seg >= BB * SS) return;
    int b = seg >> 10;

    int tcnt = g_cnt_t[seg];
    if (tcnt == 0) return;
    int toff = g_off_t[seg];
    int cnt  = g_cnt_s[seg];
    int off  = g_off_s[seg];

    const int* rows = g_rows_s + b * MM + off;
    const float* base = src + (size_t)b * MM * DD;

    float4 acc0 = {0,0,0,0}, acc1 = {0,0,0,0}, acc2 = {0,0,0,0}, acc3 = {0,0,0,0};
    int r = 0;
    for (; r + 4 <= cnt; r += 4) {
        int m0 = rows[r], m1 = rows[r+1], m2 = rows[r+2], m3 = rows[r+3];
        float4 v0 = ((const float4*)(base + (size_t)m0 * DD))[lane];
        float4 v1 = ((const float4*)(base + (size_t)m1 * DD))[lane];
        float4 v2 = ((const float4*)(base + (size_t)m2 * DD))[lane];
        float4 v3 = ((const float4*)(base + (size_t)m3 * DD))[lane];
        acc0.x += v0.x; acc0.y += v0.y; acc0.z += v0.z; acc0.w += v0.w;
        acc1.x += v1.x; acc1.y += v1.y; acc1.z += v1.z; acc1.w += v1.w;
        acc2.x += v2.x; acc2.y += v2.y; acc2.z += v2.z; acc2.w += v2.w;
        acc3.x += v3.x; acc3.y += v3.y; acc3.z += v3.z; acc3.w += v3.w;
    }
    for (; r < cnt; r++) {
        int m = rows[r];
        float4 v = ((const float4*)(base + (size_t)m * DD))[lane];
        acc0.x += v.x; acc0.y += v.y; acc0.z += v.z; acc0.w += v.w;
    }
    float inv = 1.0f / ((float)cnt + 1e-10f);
    float4 res;
    res.x = (acc0.x + acc1.x + acc2.x + acc3.x) * inv;
    res.y = (acc0.y + acc1.y + acc2.y + acc3.y) * inv;
    res.z = (acc0.z + acc1.z + acc2.z + acc3.z) * inv;
    res.w = (acc0.w + acc1.w + acc2.w + acc3.w) * inv;

    const int* trows = g_rows_t + b * NN + toff;
    float* outb = out + (size_t)b * NN * DD;
    for (int j = 0; j < tcnt; j++) {
        int n = trows[j];
        ((float4*)(outb + (size_t)n * DD))[lane] = res;
    }
}

// ---------------- launch ----------------
extern "C" void kernel_launch(void* const* d_in, const int* in_sizes, int n_in,
                              void* d_out, int out_size) {
    const int*   idx_tgt = (const int*)d_in[0];
    const int*   idx_src = (const int*)d_in[1];
    const float* src     = (const float*)d_in[2];
    float*       out     = (float*)d_out;

    k_sort        <<<NBLK, 256>>>(idx_src, idx_tgt);
    k_segsum_write<<<(BB * SS * 32 + 127) / 128, 128>>>(src, out);
}

// round 8
// speedup vs baseline: 1.0468x; 1.0468x over previous
#include <cuda_runtime.h>
#include <cuda_bf16.h>
#include <stdint.h>

#define BB 4
#define NN 2048
#define MM 8192
#define DD 128
#define SS 1024    // NUM_SEGMENTS
#define HB 16      // sort blocks per batch (source), 512 rows each
#define HBT 4      // sort blocks per batch (target), 512 rows each
#define NSRC_BLKS (BB * HB)            // 64
#define NTGT_BLKS (BB * HBT)           // 16
#define NBLK (NSRC_BLKS + NTGT_BLKS)   // 80

// ---------------- scratch (static __device__, no allocation) ----------------
__device__ int  g_blkhist_s[BB * HB * SS];
__device__ int  g_blkhist_t[BB * HBT * SS];
__device__ int2 g_meta_s[BB * SS];   // {cnt, off} for source sort
__device__ int2 g_meta_t[BB * SS];   // {cnt, off} for target sort
__device__ int  g_rows_s[BB * MM];
__device__ int  g_rows_t[BB * NN];

// ---------------- 1) per-block private histograms ----------------
// blocks 0..63: source (16/batch, 512 rows); 64..79: target (4/batch, 512 rows)
__global__ __launch_bounds__(256) void k_hist(const int* __restrict__ idx_src,
                                              const int* __restrict__ idx_tgt) {
    __shared__ int h[SS];
    const int t = threadIdx.x;
    ((int4*)h)[t] = make_int4(0, 0, 0, 0);
    __syncthreads();

    const int* in;
    int* outh;
    if (blockIdx.x < NSRC_BLKS) {
        int b = blockIdx.x >> 4, i = blockIdx.x & 15;
        in   = idx_src + b * MM + i * 512;
        outh = g_blkhist_s + (b * HB + i) * SS;
    } else {
        int u = blockIdx.x - NSRC_BLKS;
        int b = u >> 2, i = u & 3;
        in   = idx_tgt + b * NN + i * 512;
        outh = g_blkhist_t + (b * HBT + i) * SS;
    }

    int2 a = ((const int2*)in)[t];
    atomicAdd(&h[a.x], 1); atomicAdd(&h[a.y], 1);
    __syncthreads();
    ((int4*)outh)[t] = ((int4*)h)[t];
}

// ---------------- 2) scan + scatter (shared cursors, exact global offsets) ----------
__global__ __launch_bounds__(256) void k_scatter(const int* __restrict__ idx_src,
                                                 const int* __restrict__ idx_tgt) {
    __shared__ int curs[SS];
    __shared__ int wsum[8];
    const int t = threadIdx.x;
    const int lane = t & 31;
    const int w = t >> 5;

    int b, i, nblk;
    const int* hist;
    const int* in;
    int* rows;
    int2* meta;
    if (blockIdx.x < NSRC_BLKS) {
        b = blockIdx.x >> 4; i = blockIdx.x & 15; nblk = HB;
        hist = g_blkhist_s + b * HB * SS;
        in   = idx_src + b * MM + i * 512;
        rows = g_rows_s + b * MM;
        meta = g_meta_s + b * SS;
    } else {
        int u = blockIdx.x - NSRC_BLKS;
        b = u >> 2; i = u & 3; nblk = HBT;
        hist = g_blkhist_t + b * HBT * SS;
        in   = idx_tgt + b * NN + i * 512;
        rows = g_rows_t + b * NN;
        meta = g_meta_t + b * SS;
    }

    int4 tot = make_int4(0, 0, 0, 0);
    int4 pre = make_int4(0, 0, 0, 0);
    for (int j = 0; j < nblk; j++) {
        int4 h4 = ((const int4*)(hist + j * SS))[t];
        tot.x += h4.x; tot.y += h4.y; tot.z += h4.z; tot.w += h4.w;
        if (j < i) { pre.x += h4.x; pre.y += h4.y; pre.z += h4.z; pre.w += h4.w; }
    }
    int l0 = tot.x, l1 = l0 + tot.y, l2 = l1 + tot.z, l3 = l2 + tot.w;

    int inc = l3;
    #pragma unroll
    for (int d = 1; d < 32; d <<= 1) {
        int up = __shfl_up_sync(0xffffffffu, inc, d);
        if (lane >= d) inc += up;
    }
    if (lane == 31) wsum[w] = inc;
    __syncthreads();
    if (w == 0) {
        int v = (lane < 8) ? wsum[lane] : 0;
        #pragma unroll
        for (int d = 1; d < 8; d <<= 1) {
            int up = __shfl_up_sync(0xffffffffu, v, d);
            if (lane >= d) v += up;
        }
        if (lane < 8) wsum[lane] = v;
    }
    __syncthreads();
    int excl = inc - l3 + (w > 0 ? wsum[w - 1] : 0);

    int o0 = excl, o1 = excl + l0, o2 = excl + l1, o3 = excl + l2;

    if (i == 0) {
        int s = 4 * t;
        meta[s + 0] = make_int2(tot.x, o0);
        meta[s + 1] = make_int2(tot.y, o1);
        meta[s + 2] = make_int2(tot.z, o2);
        meta[s + 3] = make_int2(tot.w, o3);
    }

    curs[4 * t + 0] = o0 + pre.x;
    curs[4 * t + 1] = o1 + pre.y;
    curs[4 * t + 2] = o2 + pre.z;
    curs[4 * t + 3] = o3 + pre.w;
    __syncthreads();

    int2 a = ((const int2*)in)[t];
    int m = i * 512 + 2 * t;
    int q;
    q = atomicAdd(&curs[a.x], 1); rows[q] = m + 0;
    q = atomicAdd(&curs[a.y], 1); rows[q] = m + 1;
}

// ---------------- 3) segsum + direct write, MLP-8 ----------------
__global__ __launch_bounds__(256) void k_segsum_write(const float* __restrict__ src,
                                                      float* __restrict__ out) {
    int seg  = (blockIdx.x * blockDim.x + threadIdx.x) >> 5;  // 0..BB*SS-1
    int lane = threadIdx.x & 31;
    if (seg >= BB * SS) return;
    int b = seg >> 10;

    int2 mt = g_meta_t[seg];    // {tcnt, toff}  (independent loads,
    int2 ms = g_meta_s[seg];    // {cnt,  off}    issued in parallel)
    if (mt.x == 0) return;

    const int* rows = g_rows_s + b * MM + ms.y;
    const float* base = src + (size_t)b * MM * DD;
    int cnt = ms.x;

    float4 acc0 = {0,0,0,0}, acc1 = {0,0,0,0}, acc2 = {0,0,0,0}, acc3 = {0,0,0,0};
    int r = 0;
    for (; r + 8 <= cnt; r += 8) {
        int m0 = rows[r],   m1 = rows[r+1], m2 = rows[r+2], m3 = rows[r+3];
        int m4 = rows[r+4], m5 = rows[r+5], m6 = rows[r+6], m7 = rows[r+7];
        float4 v0 = ((const float4*)(base + (size_t)m0 * DD))[lane];
        float4 v1 = ((const float4*)(base + (size_t)m1 * DD))[lane];
        float4 v2 = ((const float4*)(base + (size_t)m2 * DD))[lane];
        float4 v3 = ((const float4*)(base + (size_t)m3 * DD))[lane];
        float4 v4 = ((const float4*)(base + (size_t)m4 * DD))[lane];
        float4 v5 = ((const float4*)(base + (size_t)m5 * DD))[lane];
        float4 v6 = ((const float4*)(base + (size_t)m6 * DD))[lane];
        float4 v7 = ((const float4*)(base + (size_t)m7 * DD))[lane];
        acc0.x += v0.x + v4.x; acc0.y += v0.y + v4.y; acc0.z += v0.z + v4.z; acc0.w += v0.w + v4.w;
        acc1.x += v1.x + v5.x; acc1.y += v1.y + v5.y; acc1.z += v1.z + v5.z; acc1.w += v1.w + v5.w;
        acc2.x += v2.x + v6.x; acc2.y += v2.y + v6.y; acc2.z += v2.z + v6.z; acc2.w += v2.w + v6.w;
        acc3.x += v3.x + v7.x; acc3.y += v3.y + v7.y; acc3.z += v3.z + v7.z; acc3.w += v3.w + v7.w;
    }
    for (; r + 4 <= cnt; r += 4) {
        int m0 = rows[r], m1 = rows[r+1], m2 = rows[r+2], m3 = rows[r+3];
        float4 v0 = ((const float4*)(base + (size_t)m0 * DD))[lane];
        float4 v1 = ((const float4*)(base + (size_t)m1 * DD))[lane];
        float4 v2 = ((const float4*)(base + (size_t)m2 * DD))[lane];
        float4 v3 = ((const float4*)(base + (size_t)m3 * DD))[lane];
        acc0.x += v0.x; acc0.y += v0.y; acc0.z += v0.z; acc0.w += v0.w;
        acc1.x += v1.x; acc1.y += v1.y; acc1.z += v1.z; acc1.w += v1.w;
        acc2.x += v2.x; acc2.y += v2.y; acc2.z += v2.z; acc2.w += v2.w;
        acc3.x += v3.x; acc3.y += v3.y; acc3.z += v3.z; acc3.w += v3.w;
    }
    for (; r < cnt; r++) {
        int m = rows[r];
        float4 v = ((const float4*)(base + (size_t)m * DD))[lane];
        acc0.x += v.x; acc0.y += v.y; acc0.z += v.z; acc0.w += v.w;
    }
    float inv = 1.0f / ((float)cnt + 1e-10f);
    float4 res;
    res.x = (acc0.x + acc1.x + acc2.x + acc3.x) * inv;
    res.y = (acc0.y + acc1.y + acc2.y + acc3.y) * inv;
    res.z = (acc0.z + acc1.z + acc2.z + acc3.z) * inv;
    res.w = (acc0.w + acc1.w + acc2.w + acc3.w) * inv;

    const int* trows = g_rows_t + b * NN + mt.y;
    float* outb = out + (size_t)b * NN * DD;
    for (int j = 0; j < mt.x; j++) {
        int n = trows[j];
        ((float4*)(outb + (size_t)n * DD))[lane] = res;
    }
}

// ---------------- launch ----------------
extern "C" void kernel_launch(void* const* d_in, const int* in_sizes, int n_in,
                              void* d_out, int out_size) {
    const int*   idx_tgt = (const int*)d_in[0];
    const int*   idx_src = (const int*)d_in[1];
    const float* src     = (const float*)d_in[2];
    float*       out     = (float*)d_out;

    k_hist        <<<NBLK, 256>>>(idx_src, idx_tgt);
    k_scatter     <<<NBLK, 256>>>(idx_src, idx_tgt);
    k_segsum_write<<<(BB * SS * 32 + 255) / 256, 256>>>(src, out);
}

// round 9
// speedup vs baseline: 1.2208x; 1.1662x over previous
#include <cuda_runtime.h>
#include <cuda_bf16.h>
#include <stdint.h>

#define BB 4
#define NN 2048
#define MM 8192
#define DD 128
#define SS 1024     // NUM_SEGMENTS
#define HB 8        // source chunks per batch, 1024 rows each
#define HBT 2       // target chunks per batch, 1024 rows each
#define NSRC_BLKS (BB * HB)            // 32
#define NTGT_BLKS (BB * HBT)           // 8
#define NBLK (NSRC_BLKS + NTGT_BLKS)   // 40
#define STAGE_CAP 96                   // max staged rows per segment (P(exceed) ~ 0)

// ---------------- scratch (static __device__, no allocation) ----------------
// meta[(b*SS+s)*CH + j] = {cnt, local_off} of segment s within chunk j
__device__ int2 g_meta_s[BB * SS * HB];
__device__ int2 g_meta_t[BB * SS * HBT];
__device__ int  g_rows_s[BB * MM];   // rows grouped by segment WITHIN each chunk
__device__ int  g_rows_t[BB * NN];

// ---------------- 1) block-local sort: hist + local scan + local scatter ----------
// blocks 0..31: source chunks; 32..39: target chunks. No cross-block deps.
__global__ __launch_bounds__(256) void k_sort(const int* __restrict__ idx_src,
                                              const int* __restrict__ idx_tgt) {
    __shared__ int sh[SS];
    __shared__ int wsum[8];
    const int t = threadIdx.x;
    const int lane = t & 31;
    const int w = t >> 5;

    const int* in;
    int*  rows;
    int2* meta;      // meta for this chunk: meta[s * CH] with CH stride
    int   ch_stride; // HB or HBT
    int   chunk;     // chunk id i (for row numbering)
    if (blockIdx.x < NSRC_BLKS) {
        int b = blockIdx.x >> 3, i = blockIdx.x & 7;
        in   = idx_src + b * MM + i * 1024;
        rows = g_rows_s + b * MM + i * 1024;
        meta = g_meta_s + (b * SS) * HB + i;
        ch_stride = HB; chunk = i;
    } else {
        int u = blockIdx.x - NSRC_BLKS;
        int b = u >> 1, i = u & 1;
        in   = idx_tgt + b * NN + i * 1024;
        rows = g_rows_t + b * NN + i * 1024;
        meta = g_meta_t + (b * SS) * HBT + i;
        ch_stride = HBT; chunk = i;
    }

    // hist
    ((int4*)sh)[t] = make_int4(0, 0, 0, 0);
    __syncthreads();
    const int4 a = ((const int4*)in)[t];
    atomicAdd(&sh[a.x], 1); atomicAdd(&sh[a.y], 1);
    atomicAdd(&sh[a.z], 1); atomicAdd(&sh[a.w], 1);
    __syncthreads();

    // local exclusive scan over this block's 1024 bins (thread owns bins 4t..4t+3)
    int4 tot = ((int4*)sh)[t];
    int l0 = tot.x, l1 = l0 + tot.y, l2 = l1 + tot.z, l3 = l2 + tot.w;
    int inc = l3;
    #pragma unroll
    for (int d = 1; d < 32; d <<= 1) {
        int up = __shfl_up_sync(0xffffffffu, inc, d);
        if (lane >= d) inc += up;
    }
    if (lane == 31) wsum[w] = inc;
    __syncthreads();
    if (w == 0) {
        int v = (lane < 8) ? wsum[lane] : 0;
        #pragma unroll
        for (int d = 1; d < 8; d <<= 1) {
            int up = __shfl_up_sync(0xffffffffu, v, d);
            if (lane >= d) v += up;
        }
        if (lane < 8) wsum[lane] = v;
    }
    __syncthreads();
    int excl = inc - l3 + (w > 0 ? wsum[w - 1] : 0);
    int o0 = excl, o1 = excl + l0, o2 = excl + l1, o3 = excl + l2;

    // publish per-chunk meta {cnt, local_off}
    int s = 4 * t;
    meta[(s + 0) * ch_stride] = make_int2(tot.x, o0);
    meta[(s + 1) * ch_stride] = make_int2(tot.y, o1);
    meta[(s + 2) * ch_stride] = make_int2(tot.z, o2);
    meta[(s + 3) * ch_stride] = make_int2(tot.w, o3);

    // cursors (thread only rewrites its own 4 bins)
    sh[s + 0] = o0; sh[s + 1] = o1; sh[s + 2] = o2; sh[s + 3] = o3;
    __syncthreads();

    // local scatter; store batch-relative row id
    int m = chunk * 1024 + 4 * t;
    int q;
    q = atomicAdd(&sh[a.x], 1); rows[q] = m + 0;
    q = atomicAdd(&sh[a.y], 1); rows[q] = m + 1;
    q = atomicAdd(&sh[a.z], 1); rows[q] = m + 2;
    q = atomicAdd(&sh[a.w], 1); rows[q] = m + 3;
}

// ---------------- 2) segsum + write: one warp per segment ----------------
__global__ __launch_bounds__(256) void k_segsum_write(const float* __restrict__ src,
                                                      float* __restrict__ out) {
    __shared__ int stage[8][STAGE_CAP];
    int seg  = (blockIdx.x * blockDim.x + threadIdx.x) >> 5;   // 0..BB*SS-1
    int lane = threadIdx.x & 31;
    int w    = (threadIdx.x >> 5) & 7;
    if (seg >= BB * SS) return;
    int b = seg >> 10;

    // one lane-parallel load covers all meta: 16 src ints + 4 tgt ints
    const int* ms_raw = (const int*)(g_meta_s + (size_t)seg * HB);
    const int* mt_raw = (const int*)(g_meta_t + (size_t)seg * HBT);
    int mv = 0;
    if (lane < 16)      mv = ms_raw[lane];
    else if (lane < 20) mv = mt_raw[lane - 16];

    int tc0 = __shfl_sync(0xffffffffu, mv, 16);
    int to0 = __shfl_sync(0xffffffffu, mv, 17);
    int tc1 = __shfl_sync(0xffffffffu, mv, 18);
    int to1 = __shfl_sync(0xffffffffu, mv, 19);
    if (tc0 + tc1 == 0) return;

    // per-chunk src counts/offsets + running prefix
    int cj[HB], oj[HB], pj[HB];
    int cnt = 0;
    #pragma unroll
    for (int j = 0; j < HB; j++) {
        cj[j] = __shfl_sync(0xffffffffu, mv, 2 * j);
        oj[j] = __shfl_sync(0xffffffffu, mv, 2 * j + 1);
        pj[j] = cnt;
        cnt += cj[j];
    }

    const float* base = src + (size_t)b * MM * DD;
    float4 acc0 = {0,0,0,0}, acc1 = {0,0,0,0}, acc2 = {0,0,0,0}, acc3 = {0,0,0,0};

    if (cnt <= STAGE_CAP) {
        // lane j stages chunk j's sub-list (independent loads across lanes)
        if (lane < HB) {
            int c = cj[lane], o = oj[lane], p = pj[lane];
            const int* rp = g_rows_s + b * MM + lane * 1024 + o;
            for (int r = 0; r < c; r++) stage[w][p + r] = rp[r];
        }
        __syncwarp();

        const int* mlist = stage[w];
        int r = 0;
        for (; r + 8 <= cnt; r += 8) {
            int m0 = mlist[r],   m1 = mlist[r+1], m2 = mlist[r+2], m3 = mlist[r+3];
            int m4 = mlist[r+4], m5 = mlist[r+5], m6 = mlist[r+6], m7 = mlist[r+7];
            float4 v0 = ((const float4*)(base + (size_t)m0 * DD))[lane];
            float4 v1 = ((const float4*)(base + (size_t)m1 * DD))[lane];
            float4 v2 = ((const float4*)(base + (size_t)m2 * DD))[lane];
            float4 v3 = ((const float4*)(base + (size_t)m3 * DD))[lane];
            float4 v4 = ((const float4*)(base + (size_t)m4 * DD))[lane];
            float4 v5 = ((const float4*)(base + (size_t)m5 * DD))[lane];
            float4 v6 = ((const float4*)(base + (size_t)m6 * DD))[lane];
            float4 v7 = ((const float4*)(base + (size_t)m7 * DD))[lane];
            acc0.x += v0.x + v4.x; acc0.y += v0.y + v4.y; acc0.z += v0.z + v4.z; acc0.w += v0.w + v4.w;
            acc1.x += v1.x + v5.x; acc1.y += v1.y + v5.y; acc1.z += v1.z + v5.z; acc1.w += v1.w + v5.w;
            acc2.x += v2.x + v6.x; acc2.y += v2.y + v6.y; acc2.z += v2.z + v6.z; acc2.w += v2.w + v6.w;
            acc3.x += v3.x + v7.x; acc3.y += v3.y + v7.y; acc3.z += v3.z + v7.z; acc3.w += v3.w + v7.w;
        }
        for (; r + 4 <= cnt; r += 4) {
            int m0 = mlist[r], m1 = mlist[r+1], m2 = mlist[r+2], m3 = mlist[r+3];
            float4 v0 = ((const float4*)(base + (size_t)m0 * DD))[lane];
            float4 v1 = ((const float4*)(base + (size_t)m1 * DD))[lane];
            float4 v2 = ((const float4*)(base + (size_t)m2 * DD))[lane];
            float4 v3 = ((const float4*)(base + (size_t)m3 * DD))[lane];
            acc0.x += v0.x; acc0.y += v0.y; acc0.z += v0.z; acc0.w += v0.w;
            acc1.x += v1.x; acc1.y += v1.y; acc1.z += v1.z; acc1.w += v1.w;
            acc2.x += v2.x; acc2.y += v2.y; acc2.z += v2.z; acc2.w += v2.w;
            acc3.x += v3.x; acc3.y += v3.y; acc3.z += v3.z; acc3.w += v3.w;
        }
        for (; r < cnt; r++) {
            int m = mlist[r];
            float4 v = ((const float4*)(base + (size_t)m * DD))[lane];
            acc0.x += v.x; acc0.y += v.y; acc0.z += v.z; acc0.w += v.w;
        }
    } else {
        // overflow fallback: direct per-chunk accumulation (practically never taken)
        #pragma unroll
        for (int j = 0; j < HB; j++) {
            const int* rp = g_rows_s + b * MM + j * 1024 + oj[j];
            for (int r = 0; r < cj[j]; r++) {
                int m = rp[r];
                float4 v = ((const float4*)(base + (size_t)m * DD))[lane];
                acc0.x += v.x; acc0.y += v.y; acc0.z += v.z; acc0.w += v.w;
            }
        }
    }

    float inv = 1.0f / ((float)cnt + 1e-10f);
    float4 res;
    res.x = (acc0.x + acc1.x + acc2.x + acc3.x) * inv;
    res.y = (acc0.y + acc1.y + acc2.y + acc3.y) * inv;
    res.z = (acc0.z + acc1.z + acc2.z + acc3.z) * inv;
    res.w = (acc0.w + acc1.w + acc2.w + acc3.w) * inv;

    // write to target rows from the 2 target sub-lists
    float* outb = out + (size_t)b * NN * DD;
    const int* tp0 = g_rows_t + b * NN + to0;
    for (int r = 0; r < tc0; r++) {
        int n = tp0[r];
        ((float4*)(outb + (size_t)n * DD))[lane] = res;
    }
    const int* tp1 = g_rows_t + b * NN + 1024 + to1;
    for (int r = 0; r < tc1; r++) {
        int n = tp1[r];
        ((float4*)(outb + (size_t)n * DD))[lane] = res;
    }
}

// ---------------- launch ----------------
extern "C" void kernel_launch(void* const* d_in, const int* in_sizes, int n_in,
                              void* d_out, int out_size) {
    const int*   idx_tgt = (const int*)d_in[0];
    const int*   idx_src = (const int*)d_in[1];
    const float* src     = (const float*)d_in[2];
    float*       out     = (float*)d_out;

    k_sort        <<<NBLK, 256>>>(idx_src, idx_tgt);
    k_segsum_write<<<(BB * SS * 32 + 255) / 256, 256>>>(src, out);
}